// round 11
// baseline (speedup 1.0000x reference)
#include <cuda_runtime.h>
#include <math.h>

#define SLEN 8192
#define EDIM 512
#define HH   512
#define G4   2048
#define HD   1024
#define KTAG 5
#define NEGV -10000.0f
#define NCTA 64           /* CTAs per direction */
#define UNITS 8           /* hidden units per CTA */
#define LTHREADS 256
#define VOCAB 50257

// ---------------- scratch (device globals: allocation-free) ----------------
__device__ float g_x[SLEN * EDIM];
__device__ float g_xp[2][SLEN * G4];
__device__ float g_hs[2][SLEN * HH];
__device__ float g_feats[SLEN * KTAG];
// packed h exchange: word = (stamp<<32)|float_bits. [dir][parity][unit]
__device__ __align__(128) unsigned long long g_hpk[2][2][HH];

// ---------------- init: publish h0 with stamp 0; sentinel parity-1 ----------
__global__ void init_kernel(const float* __restrict__ h0) {
    int i = blockIdx.x * 256 + threadIdx.x;              // 0..1023
    int dir = i >> 9, unit = i & 511;
    g_hpk[dir][0][unit] = (unsigned long long)__float_as_uint(h0[i]);
    g_hpk[dir][1][unit] = 0xFFFFFFFF00000000ull;         // matches no step
}

// ---------------- fast gate math (MUFU-based, saturation-safe) ----------------
__device__ __forceinline__ float sigf(float x) {
    return __fdividef(1.f, 1.f + __expf(-x));
}
__device__ __forceinline__ float tanhfast(float x) {
    return 1.f - __fdividef(2.f, __expf(2.f * x) + 1.f);
}

// ---------------- embedding gather ----------------
__global__ void gather_kernel(const int* __restrict__ sent,
                              const float* __restrict__ embed) {
    int t = blockIdx.x;
    unsigned v = (unsigned)sent[t];
    if (v >= (unsigned)VOCAB) v = 0u;
    const float4* src = (const float4*)(embed + (size_t)v * EDIM);
    float4* dst = (float4*)(g_x + (size_t)t * EDIM);
    dst[threadIdx.x] = src[threadIdx.x];
}

// ---------------- input projection GEMM: xp = x @ W_ih^T + b ----------------
#define BM 128
#define BN 128
#define BK 16
__global__ void __launch_bounds__(256)
gemm_kernel(const float* __restrict__ Wf, const float* __restrict__ bf,
            const float* __restrict__ Wb, const float* __restrict__ bb) {
    int dir = blockIdx.z;
    const float* W    = dir ? Wb : Wf;
    const float* bias = dir ? bb : bf;
    float* out = g_xp[dir];

    __shared__ float As[BK][BM + 4];
    __shared__ float Bs[BK][BN + 4];

    int tid = threadIdx.x;
    int m0 = blockIdx.y * BM, n0 = blockIdx.x * BN;
    int tx = tid & 15, ty = tid >> 4;

    float acc[8][8];
#pragma unroll
    for (int i = 0; i < 8; i++)
#pragma unroll
        for (int j = 0; j < 8; j++) acc[i][j] = 0.f;

    const float* Aptr = g_x + (size_t)m0 * EDIM;
    const float* Bptr = W   + (size_t)n0 * EDIM;

    for (int k0 = 0; k0 < EDIM; k0 += BK) {
#pragma unroll
        for (int it = 0; it < 2; it++) {
            int idx = tid + it * 256;
            int row = idx >> 2;
            int kc  = (idx & 3) * 4;
            float4 a = *(const float4*)(Aptr + (size_t)row * EDIM + k0 + kc);
            As[kc + 0][row] = a.x; As[kc + 1][row] = a.y;
            As[kc + 2][row] = a.z; As[kc + 3][row] = a.w;
            float4 b = *(const float4*)(Bptr + (size_t)row * EDIM + k0 + kc);
            Bs[kc + 0][row] = b.x; Bs[kc + 1][row] = b.y;
            Bs[kc + 2][row] = b.z; Bs[kc + 3][row] = b.w;
        }
        __syncthreads();
#pragma unroll
        for (int k = 0; k < BK; k++) {
            float a[8], b[8];
#pragma unroll
            for (int i = 0; i < 8; i++) a[i] = As[k][ty * 8 + i];
#pragma unroll
            for (int j = 0; j < 8; j++) b[j] = Bs[k][tx * 8 + j];
#pragma unroll
            for (int i = 0; i < 8; i++)
#pragma unroll
                for (int j = 0; j < 8; j++) acc[i][j] += a[i] * b[j];
        }
        __syncthreads();
    }
#pragma unroll
    for (int i = 0; i < 8; i++) {
        int m = m0 + ty * 8 + i;
#pragma unroll
        for (int j = 0; j < 8; j++) {
            int n = n0 + tx * 8 + j;
            out[(size_t)m * G4 + n] = acc[i][j] + bias[n];
        }
    }
}

// ---------------- persistent bidirectional LSTM scan ----------------
// 64 CTAs/dir, 8 warps/CTA (warp u <-> unit base+u). Per step t:
//   warp0 polls 512 packed (stamp|h) words of buf[t&1] with ld.acquire
//   (morally strong vs st.release -> guaranteed eventual visibility;
//    weak .cg polling livelocked in R10)
//   warp0 scatters h to smem; bar; all warps compute; lane0 gates -> h
//   h -> smem; bar; warp0 lanes<8 st.release 8 packs (stamp t+1) = one 64B line
__global__ void __launch_bounds__(LTHREADS)
lstm_kernel(const float* __restrict__ Whh_f, const float* __restrict__ Whh_b,
            const float* __restrict__ c0) {
    __shared__ float hsh[HH];
    __shared__ float h8s[UNITS];
    int dir  = blockIdx.x >> 6;
    int cb   = blockIdx.x & 63;
    int base = cb * UNITS;

    const float* Whh = dir ? Whh_b : Whh_f;
    const float* xp  = g_xp[dir];
    float* hs        = g_hs[dir];

    int tid = threadIdx.x, lane = tid & 31, wid = tid >> 5;
    int unit = base + wid;

    float wr[4][16];
#pragma unroll
    for (int g = 0; g < 4; g++) {
        const float* row = Whh + (size_t)(unit + 512 * g) * HH;
#pragma unroll
        for (int k = 0; k < 16; k++) wr[g][k] = row[lane + 32 * k];
    }

    float c = (lane == 0) ? c0[dir * HH + unit] : 0.f;

    // prefetch xp for step 0: lane g<4 holds gate g's xp value for this unit
    float xn = 0.f;
    {
        int tt = dir ? (SLEN - 1) : 0;
        if (lane < 4) xn = xp[(size_t)tt * G4 + unit + 512 * lane];
    }

    for (int t = 0; t < SLEN; t++) {
        // ---- one-hop acquire: warp0 polls packed words (stamp == t) ----
        if (wid == 0) {
            const unsigned long long* buf = g_hpk[dir][t & 1];
            unsigned stamp = (unsigned)t;
            unsigned hlo[16];
            for (;;) {
                int ok = 1;
#pragma unroll
                for (int k = 0; k < 16; k++) {
                    unsigned long long v;
                    asm volatile("ld.acquire.gpu.global.b64 %0, [%1];"
                                 : "=l"(v)
                                 : "l"(buf + lane + 32 * k) : "memory");
                    hlo[k] = (unsigned)v;
                    ok &= ((unsigned)(v >> 32) == stamp);
                }
                if (__all_sync(0xffffffffu, ok)) break;
            }
#pragma unroll
            for (int k = 0; k < 16; k++)
                hsh[lane + 32 * k] = __uint_as_float(hlo[k]);  // conflict-free
        }
        __syncthreads();                       // hsh ready for all warps

        float xv = xn;
        if (t + 1 < SLEN && lane < 4) {
            int tt = dir ? (SLEN - 2 - t) : (t + 1);
            xn = xp[(size_t)tt * G4 + unit + 512 * lane];
        }

        float p0 = 0.f, p1 = 0.f, p2 = 0.f, p3 = 0.f;
#pragma unroll
        for (int k = 0; k < 16; k++) {
            float hv = hsh[lane + 32 * k];     // conflict-free
            p0 += wr[0][k] * hv;
            p1 += wr[1][k] * hv;
            p2 += wr[2][k] * hv;
            p3 += wr[3][k] * hv;
        }
        if      (lane == 0) p0 += xv;
        else if (lane == 1) p1 += xv;
        else if (lane == 2) p2 += xv;
        else if (lane == 3) p3 += xv;
#pragma unroll
        for (int off = 16; off; off >>= 1) {
            p0 += __shfl_down_sync(0xffffffffu, p0, off);
            p1 += __shfl_down_sync(0xffffffffu, p1, off);
            p2 += __shfl_down_sync(0xffffffffu, p2, off);
            p3 += __shfl_down_sync(0xffffffffu, p3, off);
        }

        int tt = dir ? (SLEN - 1 - t) : t;
        if (lane == 0) {
            float ig = sigf(p0);
            float fg = sigf(p1);
            float gg = tanhfast(p2);
            float og = sigf(p3);
            c = fg * c + ig * gg;
            float h = og * tanhfast(c);
            hs[(size_t)tt * HH + unit] = h;
            h8s[wid] = h;
        }
        __syncthreads();                       // h8s ready; hsh reads done
        if (wid == 0 && lane < UNITS) {        // publish 8 packs = one 64B line
            unsigned long long pk =
                ((unsigned long long)(unsigned)(t + 1) << 32) |
                (unsigned long long)__float_as_uint(h8s[lane]);
            asm volatile("st.release.gpu.global.b64 [%0], %1;"
                         :: "l"(&g_hpk[dir][(t + 1) & 1][base + lane]), "l"(pk)
                         : "memory");
        }
        // next iteration's poll + bar protects hsh rewrite
    }
}

// ---------------- feats = [hf|hb] @ W_out^T + b_out ----------------
__global__ void __launch_bounds__(256)
feats_kernel(const float* __restrict__ Wout, const float* __restrict__ bout) {
    __shared__ float wsh[KTAG * HD];
    int tid = threadIdx.x;
    for (int i = tid; i < KTAG * HD; i += 256) wsh[i] = Wout[i];
    __syncthreads();

    int lane = tid & 31, wid = tid >> 5;
    int t = blockIdx.x * 8 + wid;
    const float* hf = g_hs[0] + (size_t)t * HH;
    const float* hb = g_hs[1] + (size_t)t * HH;

    float acc[KTAG];
#pragma unroll
    for (int k = 0; k < KTAG; k++) acc[k] = 0.f;
#pragma unroll
    for (int j = 0; j < 8; j++) {
        int d = j * 128 + lane * 4;
        float4 h = (j < 4) ? *(const float4*)(hf + d)
                           : *(const float4*)(hb + d - 512);
#pragma unroll
        for (int k = 0; k < KTAG; k++) {
            float4 wv = *(const float4*)&wsh[k * HD + d];
            acc[k] += h.x * wv.x + h.y * wv.y + h.z * wv.z + h.w * wv.w;
        }
    }
#pragma unroll
    for (int off = 16; off; off >>= 1)
#pragma unroll
        for (int k = 0; k < KTAG; k++)
            acc[k] += __shfl_down_sync(0xffffffffu, acc[k], off);
    if (lane == 0) {
#pragma unroll
        for (int k = 0; k < KTAG; k++)
            g_feats[(size_t)t * KTAG + k] = acc[k] + bout[k];
    }
}

// ---------------- Viterbi decode + backtrace (single CTA) ----------------
#define VCH 256
__global__ void viterbi_kernel(const float* __restrict__ trans,
                               float* __restrict__ out, int out_size) {
    extern __shared__ char vsm[];
    char*  bp = vsm;
    float* fb = (float*)(vsm + SLEN * KTAG);

    int tid = threadIdx.x, lane = tid & 31;
    float Trow[KTAG] = {0, 0, 0, 0, 0};
    float fv = NEGV;
    if (lane < KTAG) {
#pragma unroll
        for (int p = 0; p < KTAG; p++) Trow[p] = trans[lane * KTAG + p];
        fv = (lane == 3) ? 0.f : NEGV;                 // START = 3
    }

    for (int chunk = 0; chunk < SLEN / VCH; chunk++) {
        __syncthreads();
        for (int i = tid; i < VCH * KTAG; i += blockDim.x)
            fb[i] = g_feats[(size_t)chunk * VCH * KTAG + i];
        __syncthreads();
        if (tid < 32) {
            for (int i = 0; i < VCH; i++) {
                int t = chunk * VCH + i;
                float f0 = __shfl_sync(0xffffffffu, fv, 0);
                float f1 = __shfl_sync(0xffffffffu, fv, 1);
                float f2 = __shfl_sync(0xffffffffu, fv, 2);
                float f3 = __shfl_sync(0xffffffffu, fv, 3);
                float f4 = __shfl_sync(0xffffffffu, fv, 4);
                if (lane < KTAG) {
                    float best = f0 + Trow[0]; int arg = 0; float s;
                    s = f1 + Trow[1]; if (s > best) { best = s; arg = 1; }
                    s = f2 + Trow[2]; if (s > best) { best = s; arg = 2; }
                    s = f3 + Trow[3]; if (s > best) { best = s; arg = 3; }
                    s = f4 + Trow[4]; if (s > best) { best = s; arg = 4; }
                    fv = best + fb[i * KTAG + lane];
                    bp[(size_t)t * KTAG + lane] = (char)arg;
                }
            }
        }
    }
    __syncthreads();
    if (tid < 32) {
        float term = NEGV;
        if (lane < KTAG) term = fv + trans[4 * KTAG + lane];   // STOP = 4
        float t0 = __shfl_sync(0xffffffffu, term, 0);
        float t1 = __shfl_sync(0xffffffffu, term, 1);
        float t2 = __shfl_sync(0xffffffffu, term, 2);
        float t3 = __shfl_sync(0xffffffffu, term, 3);
        float t4 = __shfl_sync(0xffffffffu, term, 4);
        if (lane == 0) {
            float best = t0; int bi = 0;
            if (t1 > best) { best = t1; bi = 1; }
            if (t2 > best) { best = t2; bi = 2; }
            if (t3 > best) { best = t3; bi = 3; }
            if (t4 > best) { best = t4; bi = 4; }
            out[0] = best;
            int tag = bi;
            for (int t = SLEN - 1; t >= 0; t--) {
                if (1 + t < out_size) out[1 + t] = (float)tag;
                tag = (int)bp[(size_t)t * KTAG + tag];
            }
        }
    }
}

// ---------------- launch: positional binding (dict order) ----------------
extern "C" void kernel_launch(void* const* d_in, const int* in_sizes, int n_in,
                              void* d_out, int out_size) {
    const int*   sent  = (const int*)d_in[0];
    const float* embed = (const float*)d_in[1];
    const float* Wih_f = (const float*)d_in[2];
    const float* Whh_f = (const float*)d_in[3];
    const float* b_f   = (const float*)d_in[4];
    const float* Wih_b = (const float*)d_in[5];
    const float* Whh_b = (const float*)d_in[6];
    const float* b_b   = (const float*)d_in[7];
    const float* Wout  = (const float*)d_in[8];
    const float* bout  = (const float*)d_in[9];
    const float* trans = (const float*)d_in[10];
    const float* h0    = (const float*)d_in[11];
    const float* c0    = (const float*)d_in[12];
    float* out = (float*)d_out;

    init_kernel<<<4, 256>>>(h0);
    gather_kernel<<<SLEN, EDIM / 4>>>(sent, embed);
    dim3 gg(G4 / BN, SLEN / BM, 2);
    gemm_kernel<<<gg, 256>>>(Wih_f, b_f, Wih_b, b_b);
    lstm_kernel<<<128, LTHREADS>>>(Whh_f, Whh_b, c0);
    feats_kernel<<<SLEN / 8, 256>>>(Wout, bout);
    viterbi_kernel<<<1, 256, SLEN * KTAG + VCH * KTAG * 4>>>(trans, out, out_size);
}

// round 13
// speedup vs baseline: 3.1754x; 3.1754x over previous
#include <cuda_runtime.h>
#include <math.h>

#define SLEN 8192
#define EDIM 512
#define HH   512
#define G4   2048
#define HD   1024
#define KTAG 5
#define NEGV -10000.0f
#define NCTA 64           /* CTAs per direction */
#define UNITS 8           /* hidden units per CTA */
#define LTHREADS 256
#define VOCAB 50257

// ---------------- scratch (device globals: allocation-free) ----------------
__device__ float g_x[SLEN * EDIM];
__device__ float g_xp[2][SLEN * G4];
__device__ float g_hs[2][SLEN * HH];
__device__ float g_feats[SLEN * KTAG];
// packed h exchange: word = (stamp<<32)|float_bits. [dir][parity][unit]
__device__ __align__(128) unsigned long long g_hpk[2][2][HH];

// ---------------- init: publish h0 with stamp 0; sentinel parity-1 ----------
__global__ void init_kernel(const float* __restrict__ h0) {
    int i = blockIdx.x * 256 + threadIdx.x;              // 0..1023
    int dir = i >> 9, unit = i & 511;
    g_hpk[dir][0][unit] = (unsigned long long)__float_as_uint(h0[i]);
    g_hpk[dir][1][unit] = 0xFFFFFFFF00000000ull;         // matches no step
}

// ---------------- fast gate math (MUFU-based, saturation-safe) ----------------
__device__ __forceinline__ float sigf(float x) {
    return __fdividef(1.f, 1.f + __expf(-x));
}
__device__ __forceinline__ float tanhfast(float x) {
    return 1.f - __fdividef(2.f, __expf(2.f * x) + 1.f);
}

// ---------------- embedding gather ----------------
__global__ void gather_kernel(const int* __restrict__ sent,
                              const float* __restrict__ embed) {
    int t = blockIdx.x;
    unsigned v = (unsigned)sent[t];
    if (v >= (unsigned)VOCAB) v = 0u;
    const float4* src = (const float4*)(embed + (size_t)v * EDIM);
    float4* dst = (float4*)(g_x + (size_t)t * EDIM);
    dst[threadIdx.x] = src[threadIdx.x];
}

// ---------------- input projection GEMM: xp = x @ W_ih^T + b ----------------
#define BM 128
#define BN 128
#define BK 16
__global__ void __launch_bounds__(256)
gemm_kernel(const float* __restrict__ Wf, const float* __restrict__ bf,
            const float* __restrict__ Wb, const float* __restrict__ bb) {
    int dir = blockIdx.z;
    const float* W    = dir ? Wb : Wf;
    const float* bias = dir ? bb : bf;
    float* out = g_xp[dir];

    __shared__ float As[BK][BM + 4];
    __shared__ float Bs[BK][BN + 4];

    int tid = threadIdx.x;
    int m0 = blockIdx.y * BM, n0 = blockIdx.x * BN;
    int tx = tid & 15, ty = tid >> 4;

    float acc[8][8];
#pragma unroll
    for (int i = 0; i < 8; i++)
#pragma unroll
        for (int j = 0; j < 8; j++) acc[i][j] = 0.f;

    const float* Aptr = g_x + (size_t)m0 * EDIM;
    const float* Bptr = W   + (size_t)n0 * EDIM;

    for (int k0 = 0; k0 < EDIM; k0 += BK) {
#pragma unroll
        for (int it = 0; it < 2; it++) {
            int idx = tid + it * 256;
            int row = idx >> 2;
            int kc  = (idx & 3) * 4;
            float4 a = *(const float4*)(Aptr + (size_t)row * EDIM + k0 + kc);
            As[kc + 0][row] = a.x; As[kc + 1][row] = a.y;
            As[kc + 2][row] = a.z; As[kc + 3][row] = a.w;
            float4 b = *(const float4*)(Bptr + (size_t)row * EDIM + k0 + kc);
            Bs[kc + 0][row] = b.x; Bs[kc + 1][row] = b.y;
            Bs[kc + 2][row] = b.z; Bs[kc + 3][row] = b.w;
        }
        __syncthreads();
#pragma unroll
        for (int k = 0; k < BK; k++) {
            float a[8], b[8];
#pragma unroll
            for (int i = 0; i < 8; i++) a[i] = As[k][ty * 8 + i];
#pragma unroll
            for (int j = 0; j < 8; j++) b[j] = Bs[k][tx * 8 + j];
#pragma unroll
            for (int i = 0; i < 8; i++)
#pragma unroll
                for (int j = 0; j < 8; j++) acc[i][j] += a[i] * b[j];
        }
        __syncthreads();
    }
#pragma unroll
    for (int i = 0; i < 8; i++) {
        int m = m0 + ty * 8 + i;
#pragma unroll
        for (int j = 0; j < 8; j++) {
            int n = n0 + tx * 8 + j;
            out[(size_t)m * G4 + n] = acc[i][j] + bias[n];
        }
    }
}

// ---------------- persistent bidirectional LSTM scan ----------------
// 64 CTAs/dir, 8 warps/CTA (warp u <-> unit base+u). Per step t:
//   warp0 polls 512 packed (stamp|h) words of buf[t&1] with ld.RELAXED.gpu
//   (strong -> eventual visibility [weak .cg livelocked in R10], but
//    unordered -> the 16 loads per lane pipeline [acquire serialized in R11]).
//   Packs are self-consistent 8B words: data rides with the flag, so the
//   consumer needs no ordering; producer's st.release provides buffer safety.
//   warp0 scatters h to smem; bar; all warps compute; lane0 gates -> h
//   h -> smem; bar; warp0 lanes<8 st.release 8 packs (stamp t+1) = one 64B line
__global__ void __launch_bounds__(LTHREADS)
lstm_kernel(const float* __restrict__ Whh_f, const float* __restrict__ Whh_b,
            const float* __restrict__ c0) {
    __shared__ float hsh[HH];
    __shared__ float h8s[UNITS];
    int dir  = blockIdx.x >> 6;
    int cb   = blockIdx.x & 63;
    int base = cb * UNITS;

    const float* Whh = dir ? Whh_b : Whh_f;
    const float* xp  = g_xp[dir];
    float* hs        = g_hs[dir];

    int tid = threadIdx.x, lane = tid & 31, wid = tid >> 5;
    int unit = base + wid;

    float wr[4][16];
#pragma unroll
    for (int g = 0; g < 4; g++) {
        const float* row = Whh + (size_t)(unit + 512 * g) * HH;
#pragma unroll
        for (int k = 0; k < 16; k++) wr[g][k] = row[lane + 32 * k];
    }

    float c = (lane == 0) ? c0[dir * HH + unit] : 0.f;

    // prefetch xp for step 0: lane g<4 holds gate g's xp value for this unit
    float xn = 0.f;
    {
        int tt = dir ? (SLEN - 1) : 0;
        if (lane < 4) xn = xp[(size_t)tt * G4 + unit + 512 * lane];
    }

    for (int t = 0; t < SLEN; t++) {
        // ---- one-hop acquire: warp0 polls packed words (stamp == t) ----
        if (wid == 0) {
            const unsigned long long* buf = g_hpk[dir][t & 1];
            unsigned stamp = (unsigned)t;
            unsigned hlo[16];
            for (;;) {
                int ok = 1;
#pragma unroll
                for (int k = 0; k < 16; k++) {
                    unsigned long long v;
                    asm volatile("ld.relaxed.gpu.global.b64 %0, [%1];"
                                 : "=l"(v)
                                 : "l"(buf + lane + 32 * k) : "memory");
                    hlo[k] = (unsigned)v;
                    ok &= ((unsigned)(v >> 32) == stamp);
                }
                if (__all_sync(0xffffffffu, ok)) break;
            }
#pragma unroll
            for (int k = 0; k < 16; k++)
                hsh[lane + 32 * k] = __uint_as_float(hlo[k]);  // conflict-free
        }
        __syncthreads();                       // hsh ready for all warps

        float xv = xn;
        if (t + 1 < SLEN && lane < 4) {
            int tt = dir ? (SLEN - 2 - t) : (t + 1);
            xn = xp[(size_t)tt * G4 + unit + 512 * lane];
        }

        float p0 = 0.f, p1 = 0.f, p2 = 0.f, p3 = 0.f;
#pragma unroll
        for (int k = 0; k < 16; k++) {
            float hv = hsh[lane + 32 * k];     // conflict-free
            p0 += wr[0][k] * hv;
            p1 += wr[1][k] * hv;
            p2 += wr[2][k] * hv;
            p3 += wr[3][k] * hv;
        }
        if      (lane == 0) p0 += xv;
        else if (lane == 1) p1 += xv;
        else if (lane == 2) p2 += xv;
        else if (lane == 3) p3 += xv;
#pragma unroll
        for (int off = 16; off; off >>= 1) {
            p0 += __shfl_down_sync(0xffffffffu, p0, off);
            p1 += __shfl_down_sync(0xffffffffu, p1, off);
            p2 += __shfl_down_sync(0xffffffffu, p2, off);
            p3 += __shfl_down_sync(0xffffffffu, p3, off);
        }

        int tt = dir ? (SLEN - 1 - t) : t;
        if (lane == 0) {
            float ig = sigf(p0);
            float fg = sigf(p1);
            float gg = tanhfast(p2);
            float og = sigf(p3);
            c = fg * c + ig * gg;
            float h = og * tanhfast(c);
            hs[(size_t)tt * HH + unit] = h;
            h8s[wid] = h;
        }
        __syncthreads();                       // h8s ready; hsh reads done
        if (wid == 0 && lane < UNITS) {        // publish 8 packs = one 64B line
            unsigned long long pk =
                ((unsigned long long)(unsigned)(t + 1) << 32) |
                (unsigned long long)__float_as_uint(h8s[lane]);
            asm volatile("st.release.gpu.global.b64 [%0], %1;"
                         :: "l"(&g_hpk[dir][(t + 1) & 1][base + lane]), "l"(pk)
                         : "memory");
        }
        // next iteration's poll + bar protects hsh rewrite
    }
}

// ---------------- feats = [hf|hb] @ W_out^T + b_out ----------------
__global__ void __launch_bounds__(256)
feats_kernel(const float* __restrict__ Wout, const float* __restrict__ bout) {
    __shared__ float wsh[KTAG * HD];
    int tid = threadIdx.x;
    for (int i = tid; i < KTAG * HD; i += 256) wsh[i] = Wout[i];
    __syncthreads();

    int lane = tid & 31, wid = tid >> 5;
    int t = blockIdx.x * 8 + wid;
    const float* hf = g_hs[0] + (size_t)t * HH;
    const float* hb = g_hs[1] + (size_t)t * HH;

    float acc[KTAG];
#pragma unroll
    for (int k = 0; k < KTAG; k++) acc[k] = 0.f;
#pragma unroll
    for (int j = 0; j < 8; j++) {
        int d = j * 128 + lane * 4;
        float4 h = (j < 4) ? *(const float4*)(hf + d)
                           : *(const float4*)(hb + d - 512);
#pragma unroll
        for (int k = 0; k < KTAG; k++) {
            float4 wv = *(const float4*)&wsh[k * HD + d];
            acc[k] += h.x * wv.x + h.y * wv.y + h.z * wv.z + h.w * wv.w;
        }
    }
#pragma unroll
    for (int off = 16; off; off >>= 1)
#pragma unroll
        for (int k = 0; k < KTAG; k++)
            acc[k] += __shfl_down_sync(0xffffffffu, acc[k], off);
    if (lane == 0) {
#pragma unroll
        for (int k = 0; k < KTAG; k++)
            g_feats[(size_t)t * KTAG + k] = acc[k] + bout[k];
    }
}

// ---------------- Viterbi decode + backtrace (single CTA) ----------------
#define VCH 256
__global__ void viterbi_kernel(const float* __restrict__ trans,
                               float* __restrict__ out, int out_size) {
    extern __shared__ char vsm[];
    char*  bp = vsm;
    float* fb = (float*)(vsm + SLEN * KTAG);

    int tid = threadIdx.x, lane = tid & 31;
    float Trow[KTAG] = {0, 0, 0, 0, 0};
    float fv = NEGV;
    if (lane < KTAG) {
#pragma unroll
        for (int p = 0; p < KTAG; p++) Trow[p] = trans[lane * KTAG + p];
        fv = (lane == 3) ? 0.f : NEGV;                 // START = 3
    }

    for (int chunk = 0; chunk < SLEN / VCH; chunk++) {
        __syncthreads();
        for (int i = tid; i < VCH * KTAG; i += blockDim.x)
            fb[i] = g_feats[(size_t)chunk * VCH * KTAG + i];
        __syncthreads();
        if (tid < 32) {
            for (int i = 0; i < VCH; i++) {
                int t = chunk * VCH + i;
                float f0 = __shfl_sync(0xffffffffu, fv, 0);
                float f1 = __shfl_sync(0xffffffffu, fv, 1);
                float f2 = __shfl_sync(0xffffffffu, fv, 2);
                float f3 = __shfl_sync(0xffffffffu, fv, 3);
                float f4 = __shfl_sync(0xffffffffu, fv, 4);
                if (lane < KTAG) {
                    float best = f0 + Trow[0]; int arg = 0; float s;
                    s = f1 + Trow[1]; if (s > best) { best = s; arg = 1; }
                    s = f2 + Trow[2]; if (s > best) { best = s; arg = 2; }
                    s = f3 + Trow[3]; if (s > best) { best = s; arg = 3; }
                    s = f4 + Trow[4]; if (s > best) { best = s; arg = 4; }
                    fv = best + fb[i * KTAG + lane];
                    bp[(size_t)t * KTAG + lane] = (char)arg;
                }
            }
        }
    }
    __syncthreads();
    if (tid < 32) {
        float term = NEGV;
        if (lane < KTAG) term = fv + trans[4 * KTAG + lane];   // STOP = 4
        float t0 = __shfl_sync(0xffffffffu, term, 0);
        float t1 = __shfl_sync(0xffffffffu, term, 1);
        float t2 = __shfl_sync(0xffffffffu, term, 2);
        float t3 = __shfl_sync(0xffffffffu, term, 3);
        float t4 = __shfl_sync(0xffffffffu, term, 4);
        if (lane == 0) {
            float best = t0; int bi = 0;
            if (t1 > best) { best = t1; bi = 1; }
            if (t2 > best) { best = t2; bi = 2; }
            if (t3 > best) { best = t3; bi = 3; }
            if (t4 > best) { best = t4; bi = 4; }
            out[0] = best;
            int tag = bi;
            for (int t = SLEN - 1; t >= 0; t--) {
                if (1 + t < out_size) out[1 + t] = (float)tag;
                tag = (int)bp[(size_t)t * KTAG + tag];
            }
        }
    }
}

// ---------------- launch: positional binding (dict order) ----------------
extern "C" void kernel_launch(void* const* d_in, const int* in_sizes, int n_in,
                              void* d_out, int out_size) {
    const int*   sent  = (const int*)d_in[0];
    const float* embed = (const float*)d_in[1];
    const float* Wih_f = (const float*)d_in[2];
    const float* Whh_f = (const float*)d_in[3];
    const float* b_f   = (const float*)d_in[4];
    const float* Wih_b = (const float*)d_in[5];
    const float* Whh_b = (const float*)d_in[6];
    const float* b_b   = (const float*)d_in[7];
    const float* Wout  = (const float*)d_in[8];
    const float* bout  = (const float*)d_in[9];
    const float* trans = (const float*)d_in[10];
    const float* h0    = (const float*)d_in[11];
    const float* c0    = (const float*)d_in[12];
    float* out = (float*)d_out;

    init_kernel<<<4, 256>>>(h0);
    gather_kernel<<<SLEN, EDIM / 4>>>(sent, embed);
    dim3 gg(G4 / BN, SLEN / BM, 2);
    gemm_kernel<<<gg, 256>>>(Wih_f, b_f, Wih_b, b_b);
    lstm_kernel<<<128, LTHREADS>>>(Whh_f, Whh_b, c0);
    feats_kernel<<<SLEN / 8, 256>>>(Wout, bout);
    viterbi_kernel<<<1, 256, SLEN * KTAG + VCH * KTAG * 4>>>(trans, out, out_size);
}